// round 10
// baseline (speedup 1.0000x reference)
#include <cuda_runtime.h>
#include <math.h>

#define NB 2
#define NP 8192
#define CF 64
#define KC 64
#define KF 16
typedef unsigned long long ull;

__device__ float  d_sq[NB*NP];
__device__ float4 d_w1q[67*32];
__device__ int    d_cand[NB*NP*KC];
__device__ int    d_fidx[NB*NP*KF];
__device__ double d_curv[NB*NP];
__device__ double d_fv[NB*NP];
__device__ ull    d_key[NB*NP];
__device__ int    d_kid[NB*NP];
__device__ int    d_cidx[NB*1024];
__device__ int    d_fpsi[NB*1024];
__device__ float4 d_mask4[NB*NP];
__device__ unsigned d_maxb;

__device__ __forceinline__ unsigned monof(float f){
  unsigned u=__float_as_uint(f);
  return u ^ ((u>>31)?0xFFFFFFFFu:0x80000000u);
}
__device__ __forceinline__ float unmonof(unsigned m){
  unsigned u=(m&0x80000000u)?(m^0x80000000u):~m;
  return __uint_as_float(u);
}
__device__ __forceinline__ ull monod(double d){
  ull u=(ull)__double_as_longlong(d);
  return u ^ ((u>>63)?0xFFFFFFFFFFFFFFFFull:0x8000000000000000ull);
}

// ---- f32x2 packed helpers (ptxas never auto-fuses FFMA2; PTX-only path) ----
__device__ __forceinline__ ull pk2(float lo,float hi){
  ull d; asm("mov.b64 %0,{%1,%2};":"=l"(d):"f"(lo),"f"(hi)); return d;
}
__device__ __forceinline__ ull dup2(float x){
  ull d; asm("mov.b64 %0,{%1,%1};":"=l"(d):"f"(x)); return d;
}
__device__ __forceinline__ ull fma2(ull a,ull b,ull c){
  ull d; asm("fma.rn.f32x2 %0,%1,%2,%3;":"=l"(d):"l"(a),"l"(b),"l"(c)); return d;
}
__device__ __forceinline__ void unpk2(float& lo,float& hi,ull v){
  asm("mov.b64 {%0,%1},%2;":"=f"(lo),"=f"(hi):"l"(v));
}

// init(maxb) + w1 swizzle in one kernel (runs before k_prep's atomicMax)
__global__ void k_initw(const float* __restrict__ w1){
  int t=blockIdx.x*blockDim.x+threadIdx.x;
  if(t==0) d_maxb=0u;
  if(t>=67*32) return;
  int k=t>>5,l=t&31;
  d_w1q[t]=make_float4(w1[k*128+l],w1[k*128+l+32],w1[k*128+l+64],w1[k*128+l+96]);
}

__global__ void k_prep(const float* __restrict__ xyz){
  int i=blockIdx.x*blockDim.x+threadIdx.x;
  if(i>=NB*NP) return;
  float x=xyz[3*i],y=xyz[3*i+1],z=xyz[3*i+2];
  d_sq[i]=__fadd_rn(__fadd_rn(__fmul_rn(x,x),__fmul_rn(y,y)),__fmul_rn(z,z));
  unsigned m=monof(x),t=monof(y); if(t>m)m=t; t=monof(z); if(t>m)m=t;
  atomicMax(&d_maxb,m);
}

__device__ __forceinline__ void siftdn(ull* h,int n){
  int c=0;
  for(;;){
    int L=2*c+1; if(L>=n) break;
    int m=L; if(L+1<n && h[L+1]>h[L]) m=L+1;
    if(h[m]<=h[c]) break;
    ull t=h[m]; h[m]=h[c]; h[c]=t; c=m;
  }
}

#define KT 2048
__global__ __launch_bounds__(128) void k_knn(const float* __restrict__ xyz){
  __shared__ float4 tile[KT];
  int b=blockIdx.x>>6;
  int n=((blockIdx.x&63)<<7)|threadIdx.x;
  int base=b*NP;
  float xi=xyz[3*(base+n)],yi=xyz[3*(base+n)+1],zi=xyz[3*(base+n)+2];
  float sqi=d_sq[base+n];
  ull hp[65]; int hn=0; ull root=0xFFFFFFFFFFFFFFFFull;
  for(int t0=0;t0<NP;t0+=KT){
    __syncthreads();
    for(int j=threadIdx.x;j<KT;j+=128){
      int g=base+t0+j;
      tile[j]=make_float4(xyz[3*g],xyz[3*g+1],xyz[3*g+2],d_sq[g]);
    }
    __syncthreads();
    #pragma unroll 4
    for(int j=0;j<KT;j++){
      float4 v=tile[j];
      float dot=fmaf(zi,v.z,fmaf(yi,v.y,__fmul_rn(xi,v.x)));
      float d=__fsub_rn(__fadd_rn(sqi,v.w),__fmul_rn(2.0f,dot));
      ull key=((ull)monof(d)<<32)|(unsigned)(t0+j);
      if(hn<65){
        int c=hn++; hp[c]=key;
        while(c>0){ int pa=(c-1)>>1; if(hp[pa]<hp[c]){ull t=hp[pa];hp[pa]=hp[c];hp[c]=t;c=pa;} else break; }
        root=hp[0];
      } else if(key<root){
        hp[0]=key; siftdn(hp,65); root=hp[0];
      }
    }
  }
  for(int e=64;e>0;e--){ ull t=hp[0];hp[0]=hp[e];hp[e]=t; siftdn(hp,e); }
  int* o=d_cand+(long long)(base+n)*KC;
  for(int m=1;m<=KC;m++) o[m-1]=(int)(hp[m]&0xFFFFFFFFull);
}

__device__ __forceinline__ float gelu_e(float x){
  return 0.5f*x*(1.0f+erff(x*0.70710678118654752440f));
}

// One block = 4 points (w1 smem fill amortized 4x). 4 warps x 2 groups x 8 cand.
__global__ __launch_bounds__(128) void k_mlp(
  const float* __restrict__ xyz,const float* __restrict__ feat,
  const float* __restrict__ b1,const float* __restrict__ w2,const float* __restrict__ b2)
{
  __shared__ float4 w1s[67*32];       // 34304 B
  __shared__ float4 relq[4][136];     //  8704 B
  __shared__ float w2s[128],b1s[128];
  __shared__ float sc[64];
  int tid=threadIdx.x,w=tid>>5,l=tid&31;
  for(int i=tid;i<67*32;i+=128) w1s[i]=d_w1q[i];
  if(tid<128){ w2s[tid]=w2[tid]; b1s[tid]=b1[tid]; }
  __syncthreads();
  float b2v=b2[0];
  int p0=blockIdx.x*4;
  int b=p0>>13,base=b*NP;

  for(int pi=0;pi<4;pi++){
    int p=p0+pi;
    float xi=xyz[3*p],yi=xyz[3*p+1],zi=xyz[3*p+2];
    float f0=feat[p*CF+l],f1=feat[p*CF+32+l];

    for(int g2=0;g2<2;g2++){
      int c0=w*16+g2*8;
      int gi[8];
      #pragma unroll
      for(int c=0;c<8;c++) gi[c]=base+d_cand[(long long)p*KC+c0+c];
      float fa[8],fb[8];
      #pragma unroll
      for(int c=0;c<8;c++){ fa[c]=feat[gi[c]*CF+l]; fb[c]=feat[gi[c]*CF+32+l]; }
      __syncwarp();
      #pragma unroll
      for(int c=0;c<8;c++){ fa[c]=__fsub_rn(fa[c],f0); fb[c]=__fsub_rn(fb[c],f1); }
      relq[w][(3+l)*2+0]=make_float4(fa[0],fa[1],fa[2],fa[3]);
      relq[w][(3+l)*2+1]=make_float4(fa[4],fa[5],fa[6],fa[7]);
      relq[w][(35+l)*2+0]=make_float4(fb[0],fb[1],fb[2],fb[3]);
      relq[w][(35+l)*2+1]=make_float4(fb[4],fb[5],fb[6],fb[7]);
      if(l<3){
        float self=(l==0)?xi:((l==1)?yi:zi);
        float rx[8];
        #pragma unroll
        for(int c=0;c<8;c++) rx[c]=__fsub_rn(xyz[3*gi[c]+l],self);
        relq[w][l*2+0]=make_float4(rx[0],rx[1],rx[2],rx[3]);
        relq[w][l*2+1]=make_float4(rx[4],rx[5],rx[6],rx[7]);
      }
      __syncwarp();

      ull acc[16];
      #pragma unroll
      for(int i=0;i<16;i++) acc[i]=0ull;
      #pragma unroll 4
      for(int k=0;k<67;k++){
        float4 wf=w1s[(k<<5)|l];
        float4 q0=relq[w][2*k],q1=relq[w][2*k+1];
        ull r01=pk2(q0.x,q0.y),r23=pk2(q0.z,q0.w);
        ull r45=pk2(q1.x,q1.y),r67=pk2(q1.z,q1.w);
        ull wx=dup2(wf.x),wy=dup2(wf.y),wz=dup2(wf.z),ww=dup2(wf.w);
        acc[0] =fma2(wx,r01,acc[0]);  acc[1] =fma2(wy,r01,acc[1]);
        acc[2] =fma2(wz,r01,acc[2]);  acc[3] =fma2(ww,r01,acc[3]);
        acc[4] =fma2(wx,r23,acc[4]);  acc[5] =fma2(wy,r23,acc[5]);
        acc[6] =fma2(wz,r23,acc[6]);  acc[7] =fma2(ww,r23,acc[7]);
        acc[8] =fma2(wx,r45,acc[8]);  acc[9] =fma2(wy,r45,acc[9]);
        acc[10]=fma2(wz,r45,acc[10]); acc[11]=fma2(ww,r45,acc[11]);
        acc[12]=fma2(wx,r67,acc[12]); acc[13]=fma2(wy,r67,acc[13]);
        acc[14]=fma2(wz,r67,acc[14]); acc[15]=fma2(ww,r67,acc[15]);
      }

      #pragma unroll
      for(int pr=0;pr<4;pr++){
        float v0l,v0h,v1l,v1h,v2l,v2h,v3l,v3h;
        unpk2(v0l,v0h,acc[pr*4+0]);
        unpk2(v1l,v1h,acc[pr*4+1]);
        unpk2(v2l,v2h,acc[pr*4+2]);
        unpk2(v3l,v3h,acc[pr*4+3]);
        #pragma unroll
        for(int half=0;half<2;half++){
          float a0=half?v0h:v0l,a1=half?v1h:v1l,a2=half?v2h:v2l,a3=half?v3h:v3l;
          float h0=gelu_e(a0+b1s[l]);
          float h1=gelu_e(a1+b1s[l+32]);
          float h2=gelu_e(a2+b1s[l+64]);
          float h3=gelu_e(a3+b1s[l+96]);
          float part=fmaf(h3,w2s[l+96],fmaf(h2,w2s[l+64],fmaf(h1,w2s[l+32],h0*w2s[l])));
          #pragma unroll
          for(int off=16;off>0;off>>=1) part+=__shfl_down_sync(0xFFFFFFFFu,part,off);
          if(l==0) sc[c0+2*pr+half]=part+b2v;
        }
      }
    }
    __syncthreads();
    if(tid==0){
      float bv[16]; int bi[16]; int cnt=0;
      for(int c=0;c<KC;c++){
        float s=sc[c];
        if(cnt<16){
          int pos=cnt++;
          while(pos>0 && s>bv[pos-1]){ bv[pos]=bv[pos-1]; bi[pos]=bi[pos-1]; pos--; }
          bv[pos]=s; bi[pos]=c;
        } else if(s>bv[15]){
          int pos=15;
          while(pos>0 && s>bv[pos-1]){ bv[pos]=bv[pos-1]; bi[pos]=bi[pos-1]; pos--; }
          bv[pos]=s; bi[pos]=c;
        }
      }
      for(int r=0;r<KF;r++) d_fidx[(long long)p*KF+r]=d_cand[(long long)p*KC+bi[r]];
    }
    __syncthreads();
  }
}

__global__ __launch_bounds__(256) void k_curv(
  const float* __restrict__ xyz,const float* __restrict__ feat)
{
  int p=blockIdx.x*8+(threadIdx.x>>5);
  int l=threadIdx.x&31;
  int b=p>>13,base=b*NP;
  double c00=0,c01=0,c02=0,c11=0,c12=0,c22=0,fv=0;
  float cx=xyz[3*p],cy=xyz[3*p+1],cz=xyz[3*p+2];
  if(l<16){
    int g=base+d_fidx[(long long)p*KF+l];
    double dx=(double)__fsub_rn(xyz[3*g],cx);
    double dy=(double)__fsub_rn(xyz[3*g+1],cy);
    double dz=(double)__fsub_rn(xyz[3*g+2],cz);
    c00=dx*dx; c01=dx*dy; c02=dx*dz; c11=dy*dy; c12=dy*dz; c22=dz*dz;
    double s=0;
    for(int ch=0;ch<CF;ch++){
      float df=__fsub_rn(feat[g*CF+ch],feat[p*CF+ch]);
      s+=(double)df*(double)df;
    }
    fv=sqrt(s);
  }
  #pragma unroll
  for(int off=16;off>0;off>>=1){
    c00+=__shfl_down_sync(0xFFFFFFFFu,c00,off);
    c01+=__shfl_down_sync(0xFFFFFFFFu,c01,off);
    c02+=__shfl_down_sync(0xFFFFFFFFu,c02,off);
    c11+=__shfl_down_sync(0xFFFFFFFFu,c11,off);
    c12+=__shfl_down_sync(0xFFFFFFFFu,c12,off);
    c22+=__shfl_down_sync(0xFFFFFFFFu,c22,off);
    fv +=__shfl_down_sync(0xFFFFFFFFu,fv,off);
  }
  if(l==0){
    c00/=16.0;c01/=16.0;c02/=16.0;c11/=16.0;c12/=16.0;c22/=16.0;
    double q=(c00+c11+c22)/3.0;
    double p1=c01*c01+c02*c02+c12*c12;
    double p2=(c00-q)*(c00-q)+(c11-q)*(c11-q)+(c22-q)*(c22-q)+2.0*p1;
    double e0,e1,e2;
    if(p2<=0.0){ e0=e1=e2=q; }
    else{
      double pp=sqrt(p2/6.0),inv=1.0/pp;
      double b00=(c00-q)*inv,b11=(c11-q)*inv,b22=(c22-q)*inv;
      double b01=c01*inv,b02=c02*inv,b12=c12*inv;
      double detB=b00*(b11*b22-b12*b12)-b01*(b01*b22-b12*b02)+b02*(b01*b12-b11*b02);
      double r=detB*0.5; r=fmin(1.0,fmax(-1.0,r));
      double phi=acos(r)/3.0;
      e0=q+2.0*pp*cos(phi);
      e2=q+2.0*pp*cos(phi+2.0943951023931953);
      e1=3.0*q-e0-e2;
    }
    double s0=fabs(e0),s1=fabs(e1),s2=fabs(e2),t;
    if(s0<s1){t=s0;s0=s1;s1=t;}
    if(s1<s2){t=s1;s1=s2;s2=t;}
    if(s0<s1){t=s0;s0=s1;s1=t;}
    double l2=s0*s0,l1=s1*s1,l0=s2*s2;
    d_curv[p]=l0/(l0+l1+l2+1e-8);
    d_fv[p]=fv/16.0;
  }
}

__global__ __launch_bounds__(1024) void k_norm(){
  int b=blockIdx.x,tid=threadIdx.x;
  __shared__ double red[4][32];
  __shared__ double stats[4];
  double sc=0,sc2=0,sf=0,sf2=0;
  for(int u=0;u<8;u++){
    int i=b*NP+u*1024+tid;
    double c=d_curv[i],f=d_fv[i];
    sc+=c; sc2+=c*c; sf+=f; sf2+=f*f;
  }
  int w=tid>>5,l=tid&31;
  #pragma unroll
  for(int off=16;off>0;off>>=1){
    sc+=__shfl_down_sync(0xFFFFFFFFu,sc,off);
    sc2+=__shfl_down_sync(0xFFFFFFFFu,sc2,off);
    sf+=__shfl_down_sync(0xFFFFFFFFu,sf,off);
    sf2+=__shfl_down_sync(0xFFFFFFFFu,sf2,off);
  }
  if(l==0){ red[0][w]=sc; red[1][w]=sc2; red[2][w]=sf; red[3][w]=sf2; }
  __syncthreads();
  if(tid<32){
    double a=red[0][tid],bb=red[1][tid],c=red[2][tid],d=red[3][tid];
    #pragma unroll
    for(int off=16;off>0;off>>=1){
      a+=__shfl_down_sync(0xFFFFFFFFu,a,off);
      bb+=__shfl_down_sync(0xFFFFFFFFu,bb,off);
      c+=__shfl_down_sync(0xFFFFFFFFu,c,off);
      d+=__shfl_down_sync(0xFFFFFFFFu,d,off);
    }
    if(tid==0){
      double mc=a/NP,mf=c/NP;
      double vc=(bb-(double)NP*mc*mc)/(NP-1);
      double vf=(d-(double)NP*mf*mf)/(NP-1);
      stats[0]=mc; stats[1]=sqrt(fmax(vc,0.0));
      stats[2]=mf; stats[3]=sqrt(fmax(vf,0.0));
    }
  }
  __syncthreads();
  double mc=stats[0],sdc=stats[1],mf=stats[2],sdf=stats[3];
  for(int u=0;u<8;u++){
    int li=u*1024+tid,i=b*NP+li;
    double imp=(d_curv[i]-mc)/(sdc+1e-8)+0.5*((d_fv[i]-mf)/(sdf+1e-8));
    d_key[i]=monod(imp);
    d_kid[i]=li;
  }
}

__device__ __forceinline__ bool kgt(ull ka,int ia,ull kb,int ib){
  return ka>kb || (ka==kb && ia<ib);
}

// all bitonic sizes 2..2048 inside one 2048-chunk smem kernel
__global__ __launch_bounds__(1024) void k_sortA(){
  __shared__ ull ks[2048];
  __shared__ int is[2048];
  int chunk=blockIdx.x;
  int b=chunk>>2,cb=(chunk&3)*2048,base=b*NP+cb;
  int tid=threadIdx.x;
  for(int i=tid;i<2048;i+=1024){ ks[i]=d_key[base+i]; is[i]=d_kid[base+i]; }
  for(int size=2;size<=2048;size<<=1){
    for(int st=size>>1;st>=1;st>>=1){
      __syncthreads();
      int i=((tid&~(st-1))<<1)|(tid&(st-1));
      int j=i+st;
      bool desc=(((cb+i)&size)==0);
      ull ka=ks[i],kb=ks[j]; int ia=is[i],ib=is[j];
      if(kgt(ka,ia,kb,ib)!=desc){ ks[i]=kb;is[i]=ib;ks[j]=ka;is[j]=ia; }
    }
  }
  __syncthreads();
  for(int i=tid;i<2048;i+=1024){ d_key[base+i]=ks[i]; d_kid[base+i]=is[i]; }
}

__global__ void k_gpass(int size,int stride){
  int t=blockIdx.x*blockDim.x+threadIdx.x;
  if(t>=NB*NP) return;
  int b=t>>13,i=t&(NP-1);
  int j=i^stride;
  if(j<=i) return;
  bool desc=((i&size)==0);
  int A=b*NP+i,Bx=b*NP+j;
  ull ka=d_key[A],kb=d_key[Bx];
  int ia=d_kid[A],ib=d_kid[Bx];
  if(kgt(ka,ia,kb,ib)!=desc){
    d_key[A]=kb; d_kid[A]=ib; d_key[Bx]=ka; d_kid[Bx]=ia;
  }
}

__global__ __launch_bounds__(1024) void k_spass(int size){
  __shared__ ull ks[2048];
  __shared__ int is[2048];
  int chunk=blockIdx.x;
  int b=chunk>>2,cb=(chunk&3)*2048,base=b*NP+cb;
  int tid=threadIdx.x;
  for(int i=tid;i<2048;i+=1024){ ks[i]=d_key[base+i]; is[i]=d_kid[base+i]; }
  int start=(size>>1)<1024?(size>>1):1024;
  for(int st=start;st>=1;st>>=1){
    __syncthreads();
    int i=((tid&~(st-1))<<1)|(tid&(st-1));
    int j=i+st;
    bool desc=(((cb+i)&size)==0);
    ull ka=ks[i],kb=ks[j]; int ia=is[i],ib=is[j];
    if(kgt(ka,ia,kb,ib)!=desc){ ks[i]=kb;is[i]=ib;ks[j]=ka;is[j]=ia; }
  }
  __syncthreads();
  for(int i=tid;i<2048;i+=1024){ d_key[base+i]=ks[i]; d_kid[base+i]=is[i]; }
}

__global__ void k_maskcopy(const float* __restrict__ xyz){
  int t=blockIdx.x*blockDim.x+threadIdx.x;
  if(t>=NB*NP) return;
  d_mask4[t]=make_float4(xyz[3*t],xyz[3*t+1],xyz[3*t+2],0.f);
}

// merged: top-1024 index extraction + mask far-set
__global__ void k_maskset(){
  int t=blockIdx.x*blockDim.x+threadIdx.x;
  if(t>=NB*1024) return;
  int b=t>>10,r=t&1023;
  int idx=d_kid[b*NP+r];
  d_cidx[t]=idx;
  float far=unmonof(d_maxb)+1.0f;
  d_mask4[b*NP+idx]=make_float4(far,far,far,0.f);
}

// 512 threads, 16 pts/thread, ONE barrier per step, pivot via broadcast LDG.128
__global__ __launch_bounds__(512) void k_fps(){
  int b=blockIdx.x,tid=threadIdx.x,base=b*NP;
  __shared__ ull red[2][16];
  int w=tid>>5,l=tid&31;
  float px[16],py[16],pz[16],md[16];
  unsigned nidx[16];
  #pragma unroll
  for(int u=0;u<16;u++){
    float4 v=d_mask4[base+u*512+tid];
    px[u]=v.x; py[u]=v.y; pz[u]=v.z;
    md[u]=1e10f;
    nidx[u]=~(unsigned)(u*512+tid);
  }
  if(tid==0) d_fpsi[b*1024]=0;
  float4 pv=d_mask4[base];
  float lx=pv.x,ly=pv.y,lz=pv.z;
  for(int s=1;s<1024;s++){
    ull ku[16];
    #pragma unroll
    for(int u=0;u<16;u++){
      float dx=__fsub_rn(px[u],lx),dy=__fsub_rn(py[u],ly),dz=__fsub_rn(pz[u],lz);
      float d=__fadd_rn(__fadd_rn(__fmul_rn(dx,dx),__fmul_rn(dy,dy)),__fmul_rn(dz,dz));
      md[u]=fminf(md[u],d);
      ku[u]=((ull)__float_as_uint(md[u])<<32)|nidx[u];
    }
    // depth-4 register tree max (exact (dist desc, idx asc) order via packed key)
    #pragma unroll
    for(int st=8;st>0;st>>=1)
      #pragma unroll
      for(int u=0;u<16;u++) if(u<st && ku[u+st]>ku[u]) ku[u]=ku[u+st];
    ull best=ku[0];
    #pragma unroll
    for(int off=16;off>0;off>>=1){
      ull o=__shfl_down_sync(0xFFFFFFFFu,best,off);
      if(o>best) best=o;
    }
    if(l==0) red[s&1][w]=best;
    __syncthreads();
    ull v=red[s&1][l&15];
    #pragma unroll
    for(int off=8;off>0;off>>=1){
      ull o=__shfl_xor_sync(0xFFFFFFFFu,v,off);
      if(o>v) v=o;
    }
    unsigned wi=~(unsigned)(v&0xFFFFFFFFull);
    if(tid==0) d_fpsi[b*1024+s]=(int)wi;
    float4 nv=d_mask4[base+wi];   // L1-broadcast pivot fetch, no 2nd barrier
    lx=nv.x; ly=nv.y; lz=nv.z;
  }
}

__global__ void k_out(const float* __restrict__ xyz,float* __restrict__ out,int out_size){
  int t=blockIdx.x*blockDim.x+threadIdx.x;
  if(t>=NB*2048) return;
  int b=t>>11,r=t&2047;
  int idx=(r<1024)?d_cidx[b*1024+r]:d_fpsi[b*1024+(r-1024)];
  int g=b*NP+idx;
  if(out_size>=NB*2048*3){
    out[3*t]=xyz[3*g]; out[3*t+1]=xyz[3*g+1]; out[3*t+2]=xyz[3*g+2];
  }
  if(out_size>=NB*2048*4){
    out[NB*2048*3+t]=(float)idx;
  }
}

extern "C" void kernel_launch(void* const* d_in, const int* in_sizes, int n_in,
                              void* d_out, int out_size) {
  const float* xyz =(const float*)d_in[0];
  const float* feat=(const float*)d_in[1];
  const float* w1  =(const float*)d_in[2];
  const float* b1  =(const float*)d_in[3];
  const float* w2  =(const float*)d_in[4];
  const float* b2  =(const float*)d_in[5];
  float* out=(float*)d_out;

  k_initw<<<(67*32+255)/256,256>>>(w1);
  k_prep<<<(NB*NP+255)/256,256>>>(xyz);
  k_knn<<<NB*64,128>>>(xyz);
  k_mlp<<<NB*NP/4,128>>>(xyz,feat,b1,w2,b2);
  k_curv<<<NB*NP/8,256>>>(xyz,feat);
  k_norm<<<NB,1024>>>();
  k_sortA<<<NB*4,1024>>>();
  k_gpass<<<(NB*NP+255)/256,256>>>(4096,2048);
  k_spass<<<NB*4,1024>>>(4096);
  k_gpass<<<(NB*NP+255)/256,256>>>(8192,4096);
  k_gpass<<<(NB*NP+255)/256,256>>>(8192,2048);
  k_spass<<<NB*4,1024>>>(8192);
  k_maskcopy<<<(NB*NP+255)/256,256>>>(xyz);
  k_maskset<<<(NB*1024+255)/256,256>>>();
  k_fps<<<NB,512>>>();
  k_out<<<(NB*2048+255)/256,256>>>(xyz,out,out_size);
}

// round 12
// speedup vs baseline: 1.6856x; 1.6856x over previous
#include <cuda_runtime.h>
#include <math.h>

#define NB 2
#define NP 8192
#define CF 64
#define KC 64
#define KF 16
typedef unsigned long long ull;

__device__ float  d_sq[NB*NP];
__device__ float4 d_w1q[67*32];
__device__ int    d_cand[NB*NP*KC];
__device__ int    d_fidx[NB*NP*KF];
__device__ double d_curv[NB*NP];
__device__ double d_fv[NB*NP];
__device__ ull    d_key[NB*NP];
__device__ int    d_kid[NB*NP];
__device__ int    d_cidx[NB*1024];
__device__ int    d_fpsi[NB*1024];
__device__ float4 d_mask4[NB*NP];
__device__ unsigned d_maxb;

__device__ __forceinline__ unsigned monof(float f){
  unsigned u=__float_as_uint(f);
  return u ^ ((u>>31)?0xFFFFFFFFu:0x80000000u);
}
__device__ __forceinline__ float unmonof(unsigned m){
  unsigned u=(m&0x80000000u)?(m^0x80000000u):~m;
  return __uint_as_float(u);
}
__device__ __forceinline__ ull monod(double d){
  ull u=(ull)__double_as_longlong(d);
  return u ^ ((u>>63)?0xFFFFFFFFFFFFFFFFull:0x8000000000000000ull);
}

// ---- f32x2 packed helpers (ptxas never auto-fuses FFMA2; PTX-only path) ----
__device__ __forceinline__ ull pk2(float lo,float hi){
  ull d; asm("mov.b64 %0,{%1,%2};":"=l"(d):"f"(lo),"f"(hi)); return d;
}
__device__ __forceinline__ ull dup2(float x){
  ull d; asm("mov.b64 %0,{%1,%1};":"=l"(d):"f"(x)); return d;
}
__device__ __forceinline__ ull fma2(ull a,ull b,ull c){
  ull d; asm("fma.rn.f32x2 %0,%1,%2,%3;":"=l"(d):"l"(a),"l"(b),"l"(c)); return d;
}
__device__ __forceinline__ void unpk2(float& lo,float& hi,ull v){
  asm("mov.b64 {%0,%1},%2;":"=f"(lo),"=f"(hi):"l"(v));
}

// init(maxb) + w1 swizzle in one kernel (runs before k_prep's atomicMax)
__global__ void k_initw(const float* __restrict__ w1){
  int t=blockIdx.x*blockDim.x+threadIdx.x;
  if(t==0) d_maxb=0u;
  if(t>=67*32) return;
  int k=t>>5,l=t&31;
  d_w1q[t]=make_float4(w1[k*128+l],w1[k*128+l+32],w1[k*128+l+64],w1[k*128+l+96]);
}

__global__ void k_prep(const float* __restrict__ xyz){
  int i=blockIdx.x*blockDim.x+threadIdx.x;
  if(i>=NB*NP) return;
  float x=xyz[3*i],y=xyz[3*i+1],z=xyz[3*i+2];
  d_sq[i]=__fadd_rn(__fadd_rn(__fmul_rn(x,x),__fmul_rn(y,y)),__fmul_rn(z,z));
  unsigned m=monof(x),t=monof(y); if(t>m)m=t; t=monof(z); if(t>m)m=t;
  atomicMax(&d_maxb,m);
}

// sift-down from arbitrary root (max-heap)
__device__ __forceinline__ void siftdn2(ull* h,int n,int r){
  int c=r;
  for(;;){
    int L=2*c+1; if(L>=n) break;
    int m=L; if(L+1<n && h[L+1]>h[L]) m=L+1;
    if(h[m]<=h[c]) break;
    ull t=h[m]; h[m]=h[c]; h[c]=t; c=m;
  }
}

#define KT 2048
// Top-65 via two-level 5x13 flat array: insert = overwrite tracked max slot,
// streaming rescan of 13 (pipelined LDL) + 5 group maxima. No dependent-chain
// heap siftdn on the hot path.
__global__ __launch_bounds__(128) void k_knn(const float* __restrict__ xyz){
  __shared__ float4 tile[KT];
  int b=blockIdx.x>>6;
  int n=((blockIdx.x&63)<<7)|threadIdx.x;
  int base=b*NP;
  float xi=xyz[3*(base+n)],yi=xyz[3*(base+n)+1],zi=xyz[3*(base+n)+2];
  float sqi=d_sq[base+n];

  ull arr[65];
  ull gm[5]; int gmi[5];
  #pragma unroll
  for(int i=0;i<65;i++) arr[i]=0xFFFFFFFFFFFFFFFFull;
  #pragma unroll
  for(int g=0;g<5;g++){ gm[g]=0xFFFFFFFFFFFFFFFFull; gmi[g]=0; }
  ull gmax=0xFFFFFFFFFFFFFFFFull; int gmaxg=0;

  for(int t0=0;t0<NP;t0+=KT){
    __syncthreads();
    for(int j=threadIdx.x;j<KT;j+=128){
      int g=base+t0+j;
      tile[j]=make_float4(xyz[3*g],xyz[3*g+1],xyz[3*g+2],d_sq[g]);
    }
    __syncthreads();
    #pragma unroll 4
    for(int j=0;j<KT;j++){
      float4 v=tile[j];
      float dot=fmaf(zi,v.z,fmaf(yi,v.y,__fmul_rn(xi,v.x)));
      float d=__fsub_rn(__fadd_rn(sqi,v.w),__fmul_rn(2.0f,dot));
      ull key=((ull)monof(d)<<32)|(unsigned)(t0+j);
      if(key<gmax){
        int g=gmaxg, gb=g*13;
        arr[gb+gmi[g]]=key;
        ull m=0; int mi=0;
        #pragma unroll
        for(int i=0;i<13;i++){ ull vv=arr[gb+i]; if(vv>m){m=vv;mi=i;} }
        gm[g]=m; gmi[g]=mi;
        ull nm=0; int ng=0;
        #pragma unroll
        for(int g2=0;g2<5;g2++){ if(gm[g2]>nm){nm=gm[g2];ng=g2;} }
        gmax=nm; gmaxg=ng;
      }
    }
  }

  // one-time exact ascending sort of the 65 survivors (heapsort, same order
  // semantics as before: packed key = (d asc, idx asc))
  ull hp[65];
  #pragma unroll
  for(int i=0;i<65;i++) hp[i]=arr[i];
  for(int s=31;s>=0;s--) siftdn2(hp,65,s);
  for(int e=64;e>0;e--){ ull t=hp[0];hp[0]=hp[e];hp[e]=t; siftdn2(hp,e,0); }
  int* o=d_cand+(long long)(base+n)*KC;
  for(int m=1;m<=KC;m++) o[m-1]=(int)(hp[m]&0xFFFFFFFFull);
}

__device__ __forceinline__ float gelu_e(float x){
  return 0.5f*x*(1.0f+erff(x*0.70710678118654752440f));
}

// One block = 4 points (w1 smem fill amortized 4x). 4 warps x 2 groups x 8 cand.
__global__ __launch_bounds__(128) void k_mlp(
  const float* __restrict__ xyz,const float* __restrict__ feat,
  const float* __restrict__ b1,const float* __restrict__ w2,const float* __restrict__ b2)
{
  __shared__ float4 w1s[67*32];       // 34304 B
  __shared__ float4 relq[4][136];     //  8704 B
  __shared__ float w2s[128],b1s[128];
  __shared__ float sc[64];
  int tid=threadIdx.x,w=tid>>5,l=tid&31;
  for(int i=tid;i<67*32;i+=128) w1s[i]=d_w1q[i];
  if(tid<128){ w2s[tid]=w2[tid]; b1s[tid]=b1[tid]; }
  __syncthreads();
  float b2v=b2[0];
  int p0=blockIdx.x*4;
  int b=p0>>13,base=b*NP;

  for(int pi=0;pi<4;pi++){
    int p=p0+pi;
    float xi=xyz[3*p],yi=xyz[3*p+1],zi=xyz[3*p+2];
    float f0=feat[p*CF+l],f1=feat[p*CF+32+l];

    for(int g2=0;g2<2;g2++){
      int c0=w*16+g2*8;
      int gi[8];
      #pragma unroll
      for(int c=0;c<8;c++) gi[c]=base+d_cand[(long long)p*KC+c0+c];
      float fa[8],fb[8];
      #pragma unroll
      for(int c=0;c<8;c++){ fa[c]=feat[gi[c]*CF+l]; fb[c]=feat[gi[c]*CF+32+l]; }
      __syncwarp();
      #pragma unroll
      for(int c=0;c<8;c++){ fa[c]=__fsub_rn(fa[c],f0); fb[c]=__fsub_rn(fb[c],f1); }
      relq[w][(3+l)*2+0]=make_float4(fa[0],fa[1],fa[2],fa[3]);
      relq[w][(3+l)*2+1]=make_float4(fa[4],fa[5],fa[6],fa[7]);
      relq[w][(35+l)*2+0]=make_float4(fb[0],fb[1],fb[2],fb[3]);
      relq[w][(35+l)*2+1]=make_float4(fb[4],fb[5],fb[6],fb[7]);
      if(l<3){
        float self=(l==0)?xi:((l==1)?yi:zi);
        float rx[8];
        #pragma unroll
        for(int c=0;c<8;c++) rx[c]=__fsub_rn(xyz[3*gi[c]+l],self);
        relq[w][l*2+0]=make_float4(rx[0],rx[1],rx[2],rx[3]);
        relq[w][l*2+1]=make_float4(rx[4],rx[5],rx[6],rx[7]);
      }
      __syncwarp();

      ull acc[16];
      #pragma unroll
      for(int i=0;i<16;i++) acc[i]=0ull;
      #pragma unroll 4
      for(int k=0;k<67;k++){
        float4 wf=w1s[(k<<5)|l];
        float4 q0=relq[w][2*k],q1=relq[w][2*k+1];
        ull r01=pk2(q0.x,q0.y),r23=pk2(q0.z,q0.w);
        ull r45=pk2(q1.x,q1.y),r67=pk2(q1.z,q1.w);
        ull wx=dup2(wf.x),wy=dup2(wf.y),wz=dup2(wf.z),ww=dup2(wf.w);
        acc[0] =fma2(wx,r01,acc[0]);  acc[1] =fma2(wy,r01,acc[1]);
        acc[2] =fma2(wz,r01,acc[2]);  acc[3] =fma2(ww,r01,acc[3]);
        acc[4] =fma2(wx,r23,acc[4]);  acc[5] =fma2(wy,r23,acc[5]);
        acc[6] =fma2(wz,r23,acc[6]);  acc[7] =fma2(ww,r23,acc[7]);
        acc[8] =fma2(wx,r45,acc[8]);  acc[9] =fma2(wy,r45,acc[9]);
        acc[10]=fma2(wz,r45,acc[10]); acc[11]=fma2(ww,r45,acc[11]);
        acc[12]=fma2(wx,r67,acc[12]); acc[13]=fma2(wy,r67,acc[13]);
        acc[14]=fma2(wz,r67,acc[14]); acc[15]=fma2(ww,r67,acc[15]);
      }

      #pragma unroll
      for(int pr=0;pr<4;pr++){
        float v0l,v0h,v1l,v1h,v2l,v2h,v3l,v3h;
        unpk2(v0l,v0h,acc[pr*4+0]);
        unpk2(v1l,v1h,acc[pr*4+1]);
        unpk2(v2l,v2h,acc[pr*4+2]);
        unpk2(v3l,v3h,acc[pr*4+3]);
        #pragma unroll
        for(int half=0;half<2;half++){
          float a0=half?v0h:v0l,a1=half?v1h:v1l,a2=half?v2h:v2l,a3=half?v3h:v3l;
          float h0=gelu_e(a0+b1s[l]);
          float h1=gelu_e(a1+b1s[l+32]);
          float h2=gelu_e(a2+b1s[l+64]);
          float h3=gelu_e(a3+b1s[l+96]);
          float part=fmaf(h3,w2s[l+96],fmaf(h2,w2s[l+64],fmaf(h1,w2s[l+32],h0*w2s[l])));
          #pragma unroll
          for(int off=16;off>0;off>>=1) part+=__shfl_down_sync(0xFFFFFFFFu,part,off);
          if(l==0) sc[c0+2*pr+half]=part+b2v;
        }
      }
    }
    __syncthreads();
    if(tid==0){
      float bv[16]; int bi[16]; int cnt=0;
      for(int c=0;c<KC;c++){
        float s=sc[c];
        if(cnt<16){
          int pos=cnt++;
          while(pos>0 && s>bv[pos-1]){ bv[pos]=bv[pos-1]; bi[pos]=bi[pos-1]; pos--; }
          bv[pos]=s; bi[pos]=c;
        } else if(s>bv[15]){
          int pos=15;
          while(pos>0 && s>bv[pos-1]){ bv[pos]=bv[pos-1]; bi[pos]=bi[pos-1]; pos--; }
          bv[pos]=s; bi[pos]=c;
        }
      }
      for(int r=0;r<KF;r++) d_fidx[(long long)p*KF+r]=d_cand[(long long)p*KC+bi[r]];
    }
    __syncthreads();
  }
}

__global__ __launch_bounds__(256) void k_curv(
  const float* __restrict__ xyz,const float* __restrict__ feat)
{
  int p=blockIdx.x*8+(threadIdx.x>>5);
  int l=threadIdx.x&31;
  int b=p>>13,base=b*NP;
  double c00=0,c01=0,c02=0,c11=0,c12=0,c22=0,fv=0;
  float cx=xyz[3*p],cy=xyz[3*p+1],cz=xyz[3*p+2];
  if(l<16){
    int g=base+d_fidx[(long long)p*KF+l];
    double dx=(double)__fsub_rn(xyz[3*g],cx);
    double dy=(double)__fsub_rn(xyz[3*g+1],cy);
    double dz=(double)__fsub_rn(xyz[3*g+2],cz);
    c00=dx*dx; c01=dx*dy; c02=dx*dz; c11=dy*dy; c12=dy*dz; c22=dz*dz;
    double s=0;
    for(int ch=0;ch<CF;ch++){
      float df=__fsub_rn(feat[g*CF+ch],feat[p*CF+ch]);
      s+=(double)df*(double)df;
    }
    fv=sqrt(s);
  }
  #pragma unroll
  for(int off=16;off>0;off>>=1){
    c00+=__shfl_down_sync(0xFFFFFFFFu,c00,off);
    c01+=__shfl_down_sync(0xFFFFFFFFu,c01,off);
    c02+=__shfl_down_sync(0xFFFFFFFFu,c02,off);
    c11+=__shfl_down_sync(0xFFFFFFFFu,c11,off);
    c12+=__shfl_down_sync(0xFFFFFFFFu,c12,off);
    c22+=__shfl_down_sync(0xFFFFFFFFu,c22,off);
    fv +=__shfl_down_sync(0xFFFFFFFFu,fv,off);
  }
  if(l==0){
    c00/=16.0;c01/=16.0;c02/=16.0;c11/=16.0;c12/=16.0;c22/=16.0;
    double q=(c00+c11+c22)/3.0;
    double p1=c01*c01+c02*c02+c12*c12;
    double p2=(c00-q)*(c00-q)+(c11-q)*(c11-q)+(c22-q)*(c22-q)+2.0*p1;
    double e0,e1,e2;
    if(p2<=0.0){ e0=e1=e2=q; }
    else{
      double pp=sqrt(p2/6.0),inv=1.0/pp;
      double b00=(c00-q)*inv,b11=(c11-q)*inv,b22=(c22-q)*inv;
      double b01=c01*inv,b02=c02*inv,b12=c12*inv;
      double detB=b00*(b11*b22-b12*b12)-b01*(b01*b22-b12*b02)+b02*(b01*b12-b11*b02);
      double r=detB*0.5; r=fmin(1.0,fmax(-1.0,r));
      double phi=acos(r)/3.0;
      e0=q+2.0*pp*cos(phi);
      e2=q+2.0*pp*cos(phi+2.0943951023931953);
      e1=3.0*q-e0-e2;
    }
    double s0=fabs(e0),s1=fabs(e1),s2=fabs(e2),t;
    if(s0<s1){t=s0;s0=s1;s1=t;}
    if(s1<s2){t=s1;s1=s2;s2=t;}
    if(s0<s1){t=s0;s0=s1;s1=t;}
    double l2=s0*s0,l1=s1*s1,l0=s2*s2;
    d_curv[p]=l0/(l0+l1+l2+1e-8);
    d_fv[p]=fv/16.0;
  }
}

__global__ __launch_bounds__(1024) void k_norm(){
  int b=blockIdx.x,tid=threadIdx.x;
  __shared__ double red[4][32];
  __shared__ double stats[4];
  double sc=0,sc2=0,sf=0,sf2=0;
  for(int u=0;u<8;u++){
    int i=b*NP+u*1024+tid;
    double c=d_curv[i],f=d_fv[i];
    sc+=c; sc2+=c*c; sf+=f; sf2+=f*f;
  }
  int w=tid>>5,l=tid&31;
  #pragma unroll
  for(int off=16;off>0;off>>=1){
    sc+=__shfl_down_sync(0xFFFFFFFFu,sc,off);
    sc2+=__shfl_down_sync(0xFFFFFFFFu,sc2,off);
    sf+=__shfl_down_sync(0xFFFFFFFFu,sf,off);
    sf2+=__shfl_down_sync(0xFFFFFFFFu,sf2,off);
  }
  if(l==0){ red[0][w]=sc; red[1][w]=sc2; red[2][w]=sf; red[3][w]=sf2; }
  __syncthreads();
  if(tid<32){
    double a=red[0][tid],bb=red[1][tid],c=red[2][tid],d=red[3][tid];
    #pragma unroll
    for(int off=16;off>0;off>>=1){
      a+=__shfl_down_sync(0xFFFFFFFFu,a,off);
      bb+=__shfl_down_sync(0xFFFFFFFFu,bb,off);
      c+=__shfl_down_sync(0xFFFFFFFFu,c,off);
      d+=__shfl_down_sync(0xFFFFFFFFu,d,off);
    }
    if(tid==0){
      double mc=a/NP,mf=c/NP;
      double vc=(bb-(double)NP*mc*mc)/(NP-1);
      double vf=(d-(double)NP*mf*mf)/(NP-1);
      stats[0]=mc; stats[1]=sqrt(fmax(vc,0.0));
      stats[2]=mf; stats[3]=sqrt(fmax(vf,0.0));
    }
  }
  __syncthreads();
  double mc=stats[0],sdc=stats[1],mf=stats[2],sdf=stats[3];
  for(int u=0;u<8;u++){
    int li=u*1024+tid,i=b*NP+li;
    double imp=(d_curv[i]-mc)/(sdc+1e-8)+0.5*((d_fv[i]-mf)/(sdf+1e-8));
    d_key[i]=monod(imp);
    d_kid[i]=li;
  }
}

__device__ __forceinline__ bool kgt(ull ka,int ia,ull kb,int ib){
  return ka>kb || (ka==kb && ia<ib);
}

// all bitonic sizes 2..2048 inside one 2048-chunk smem kernel
__global__ __launch_bounds__(1024) void k_sortA(){
  __shared__ ull ks[2048];
  __shared__ int is[2048];
  int chunk=blockIdx.x;
  int b=chunk>>2,cb=(chunk&3)*2048,base=b*NP+cb;
  int tid=threadIdx.x;
  for(int i=tid;i<2048;i+=1024){ ks[i]=d_key[base+i]; is[i]=d_kid[base+i]; }
  for(int size=2;size<=2048;size<<=1){
    for(int st=size>>1;st>=1;st>>=1){
      __syncthreads();
      int i=((tid&~(st-1))<<1)|(tid&(st-1));
      int j=i+st;
      bool desc=(((cb+i)&size)==0);
      ull ka=ks[i],kb=ks[j]; int ia=is[i],ib=is[j];
      if(kgt(ka,ia,kb,ib)!=desc){ ks[i]=kb;is[i]=ib;ks[j]=ka;is[j]=ia; }
    }
  }
  __syncthreads();
  for(int i=tid;i<2048;i+=1024){ d_key[base+i]=ks[i]; d_kid[base+i]=is[i]; }
}

__global__ void k_gpass(int size,int stride){
  int t=blockIdx.x*blockDim.x+threadIdx.x;
  if(t>=NB*NP) return;
  int b=t>>13,i=t&(NP-1);
  int j=i^stride;
  if(j<=i) return;
  bool desc=((i&size)==0);
  int A=b*NP+i,Bx=b*NP+j;
  ull ka=d_key[A],kb=d_key[Bx];
  int ia=d_kid[A],ib=d_kid[Bx];
  if(kgt(ka,ia,kb,ib)!=desc){
    d_key[A]=kb; d_kid[A]=ib; d_key[Bx]=ka; d_kid[Bx]=ia;
  }
}

__global__ __launch_bounds__(1024) void k_spass(int size){
  __shared__ ull ks[2048];
  __shared__ int is[2048];
  int chunk=blockIdx.x;
  int b=chunk>>2,cb=(chunk&3)*2048,base=b*NP+cb;
  int tid=threadIdx.x;
  for(int i=tid;i<2048;i+=1024){ ks[i]=d_key[base+i]; is[i]=d_kid[base+i]; }
  int start=(size>>1)<1024?(size>>1):1024;
  for(int st=start;st>=1;st>>=1){
    __syncthreads();
    int i=((tid&~(st-1))<<1)|(tid&(st-1));
    int j=i+st;
    bool desc=(((cb+i)&size)==0);
    ull ka=ks[i],kb=ks[j]; int ia=is[i],ib=is[j];
    if(kgt(ka,ia,kb,ib)!=desc){ ks[i]=kb;is[i]=ib;ks[j]=ka;is[j]=ia; }
  }
  __syncthreads();
  for(int i=tid;i<2048;i+=1024){ d_key[base+i]=ks[i]; d_kid[base+i]=is[i]; }
}

__global__ void k_maskcopy(const float* __restrict__ xyz){
  int t=blockIdx.x*blockDim.x+threadIdx.x;
  if(t>=NB*NP) return;
  d_mask4[t]=make_float4(xyz[3*t],xyz[3*t+1],xyz[3*t+2],0.f);
}

// merged: top-1024 index extraction + mask far-set
__global__ void k_maskset(){
  int t=blockIdx.x*blockDim.x+threadIdx.x;
  if(t>=NB*1024) return;
  int b=t>>10,r=t&1023;
  int idx=d_kid[b*NP+r];
  d_cidx[t]=idx;
  float far=unmonof(d_maxb)+1.0f;
  d_mask4[b*NP+idx]=make_float4(far,far,far,0.f);
}

// 512 threads, 16 pts/thread, ONE barrier per step, pivot via broadcast LDG.128
__global__ __launch_bounds__(512) void k_fps(){
  int b=blockIdx.x,tid=threadIdx.x,base=b*NP;
  __shared__ ull red[2][16];
  int w=tid>>5,l=tid&31;
  float px[16],py[16],pz[16],md[16];
  unsigned nidx[16];
  #pragma unroll
  for(int u=0;u<16;u++){
    float4 v=d_mask4[base+u*512+tid];
    px[u]=v.x; py[u]=v.y; pz[u]=v.z;
    md[u]=1e10f;
    nidx[u]=~(unsigned)(u*512+tid);
  }
  if(tid==0) d_fpsi[b*1024]=0;
  float4 pv=d_mask4[base];
  float lx=pv.x,ly=pv.y,lz=pv.z;
  for(int s=1;s<1024;s++){
    ull ku[16];
    #pragma unroll
    for(int u=0;u<16;u++){
      float dx=__fsub_rn(px[u],lx),dy=__fsub_rn(py[u],ly),dz=__fsub_rn(pz[u],lz);
      float d=__fadd_rn(__fadd_rn(__fmul_rn(dx,dx),__fmul_rn(dy,dy)),__fmul_rn(dz,dz));
      md[u]=fminf(md[u],d);
      ku[u]=((ull)__float_as_uint(md[u])<<32)|nidx[u];
    }
    #pragma unroll
    for(int st=8;st>0;st>>=1)
      #pragma unroll
      for(int u=0;u<16;u++) if(u<st && ku[u+st]>ku[u]) ku[u]=ku[u+st];
    ull best=ku[0];
    #pragma unroll
    for(int off=16;off>0;off>>=1){
      ull o=__shfl_down_sync(0xFFFFFFFFu,best,off);
      if(o>best) best=o;
    }
    if(l==0) red[s&1][w]=best;
    __syncthreads();
    ull v=red[s&1][l&15];
    #pragma unroll
    for(int off=8;off>0;off>>=1){
      ull o=__shfl_xor_sync(0xFFFFFFFFu,v,off);
      if(o>v) v=o;
    }
    unsigned wi=~(unsigned)(v&0xFFFFFFFFull);
    if(tid==0) d_fpsi[b*1024+s]=(int)wi;
    float4 nv=d_mask4[base+wi];
    lx=nv.x; ly=nv.y; lz=nv.z;
  }
}

__global__ void k_out(const float* __restrict__ xyz,float* __restrict__ out,int out_size){
  int t=blockIdx.x*blockDim.x+threadIdx.x;
  if(t>=NB*2048) return;
  int b=t>>11,r=t&2047;
  int idx=(r<1024)?d_cidx[b*1024+r]:d_fpsi[b*1024+(r-1024)];
  int g=b*NP+idx;
  if(out_size>=NB*2048*3){
    out[3*t]=xyz[3*g]; out[3*t+1]=xyz[3*g+1]; out[3*t+2]=xyz[3*g+2];
  }
  if(out_size>=NB*2048*4){
    out[NB*2048*3+t]=(float)idx;
  }
}

extern "C" void kernel_launch(void* const* d_in, const int* in_sizes, int n_in,
                              void* d_out, int out_size) {
  const float* xyz =(const float*)d_in[0];
  const float* feat=(const float*)d_in[1];
  const float* w1  =(const float*)d_in[2];
  const float* b1  =(const float*)d_in[3];
  const float* w2  =(const float*)d_in[4];
  const float* b2  =(const float*)d_in[5];
  float* out=(float*)d_out;

  k_initw<<<(67*32+255)/256,256>>>(w1);
  k_prep<<<(NB*NP+255)/256,256>>>(xyz);
  k_knn<<<NB*64,128>>>(xyz);
  k_mlp<<<NB*NP/4,128>>>(xyz,feat,b1,w2,b2);
  k_curv<<<NB*NP/8,256>>>(xyz,feat);
  k_norm<<<NB,1024>>>();
  k_sortA<<<NB*4,1024>>>();
  k_gpass<<<(NB*NP+255)/256,256>>>(4096,2048);
  k_spass<<<NB*4,1024>>>(4096);
  k_gpass<<<(NB*NP+255)/256,256>>>(8192,4096);
  k_gpass<<<(NB*NP+255)/256,256>>>(8192,2048);
  k_spass<<<NB*4,1024>>>(8192);
  k_maskcopy<<<(NB*NP+255)/256,256>>>(xyz);
  k_maskset<<<(NB*1024+255)/256,256>>>();
  k_fps<<<NB,512>>>();
  k_out<<<(NB*2048+255)/256,256>>>(xyz,out,out_size);
}

// round 16
// speedup vs baseline: 3.6326x; 2.1550x over previous
#include <cuda_runtime.h>
#include <math.h>

#define NB 2
#define NP 8192
#define CF 64
#define KC 64
#define KF 16
typedef unsigned long long ull;

__device__ float  d_sq[NB*NP];
__device__ float4 d_w1q[67*32];
__device__ int    d_cand[NB*NP*KC];
__device__ int    d_fidx[NB*NP*KF];
__device__ double d_curv[NB*NP];
__device__ double d_fv[NB*NP];
__device__ ull    d_key[NB*NP];
__device__ int    d_kid[NB*NP];
__device__ int    d_cidx[NB*1024];
__device__ int    d_fpsi[NB*1024];
__device__ float4 d_mask4[NB*NP];
__device__ unsigned d_maxb;

__device__ __forceinline__ unsigned monof(float f){
  unsigned u=__float_as_uint(f);
  return u ^ ((u>>31)?0xFFFFFFFFu:0x80000000u);
}
__device__ __forceinline__ float unmonof(unsigned m){
  unsigned u=(m&0x80000000u)?(m^0x80000000u):~m;
  return __uint_as_float(u);
}
__device__ __forceinline__ ull monod(double d){
  ull u=(ull)__double_as_longlong(d);
  return u ^ ((u>>63)?0xFFFFFFFFFFFFFFFFull:0x8000000000000000ull);
}

// ---- f32x2 packed helpers ----
__device__ __forceinline__ ull pk2(float lo,float hi){
  ull d; asm("mov.b64 %0,{%1,%2};":"=l"(d):"f"(lo),"f"(hi)); return d;
}
__device__ __forceinline__ ull dup2(float x){
  ull d; asm("mov.b64 %0,{%1,%1};":"=l"(d):"f"(x)); return d;
}
__device__ __forceinline__ ull fma2(ull a,ull b,ull c){
  ull d; asm("fma.rn.f32x2 %0,%1,%2,%3;":"=l"(d):"l"(a),"l"(b),"l"(c)); return d;
}
__device__ __forceinline__ void unpk2(float& lo,float& hi,ull v){
  asm("mov.b64 {%0,%1},%2;":"=f"(lo),"=f"(hi):"l"(v));
}

__global__ void k_initw(const float* __restrict__ w1){
  int t=blockIdx.x*blockDim.x+threadIdx.x;
  if(t==0) d_maxb=0u;
  if(t>=67*32) return;
  int k=t>>5,l=t&31;
  d_w1q[t]=make_float4(w1[k*128+l],w1[k*128+l+32],w1[k*128+l+64],w1[k*128+l+96]);
}

__global__ void k_prep(const float* __restrict__ xyz){
  int i=blockIdx.x*blockDim.x+threadIdx.x;
  if(i>=NB*NP) return;
  float x=xyz[3*i],y=xyz[3*i+1],z=xyz[3*i+2];
  d_sq[i]=__fadd_rn(__fadd_rn(__fmul_rn(x,x),__fmul_rn(y,y)),__fmul_rn(z,z));
  unsigned m=monof(x),t=monof(y); if(t>m)m=t; t=monof(z); if(t>m)m=t;
  atomicMax(&d_maxb,m);
}

// Warp-per-point exact top-65 via 3-pass 8-bit radix histogram + collect.
// Identical distance formula + key packing as the flat version -> bit-identical d_cand.
__global__ __launch_bounds__(256) void k_knn(const float* __restrict__ xyz){
  __shared__ float4 tile[2048];
  __shared__ int hist[8][256];
  __shared__ ull buf[8][128];
  __shared__ int cnt[8];
  int tid=threadIdx.x,w=tid>>5,l=tid&31;
  int p=blockIdx.x*8+w;
  int b=p>>13,n=p&(NP-1),base=b*NP;
  float xi=xyz[3*(base+n)],yi=xyz[3*(base+n)+1],zi=xyz[3*(base+n)+2];
  float sqi=d_sq[base+n];
  unsigned pfx=0; int cbase=0;

  for(int pass=0;pass<3;pass++){
    for(int i=l;i<256;i+=32) hist[w][i]=0;
    __syncwarp();
    for(int t0=0;t0<NP;t0+=2048){
      __syncthreads();
      for(int j=tid;j<2048;j+=256){
        int g=base+t0+j;
        tile[j]=make_float4(xyz[3*g],xyz[3*g+1],xyz[3*g+2],d_sq[g]);
      }
      __syncthreads();
      for(int j=l;j<2048;j+=32){
        float4 v=tile[j];
        float dot=fmaf(zi,v.z,fmaf(yi,v.y,__fmul_rn(xi,v.x)));
        float d=__fsub_rn(__fadd_rn(sqi,v.w),__fmul_rn(2.0f,dot));
        unsigned u=monof(d);
        bool in; int bin;
        if(pass==0){ in=true; bin=(int)(u>>24); }
        else if(pass==1){ in=((u>>24)==pfx); bin=(int)((u>>16)&255u); }
        else { in=((u>>16)==pfx); bin=(int)((u>>8)&255u); }
        if(in) atomicAdd(&hist[w][bin],1);
      }
    }
    __syncwarp();
    int s=0;
    #pragma unroll
    for(int i=0;i<8;i++) s+=hist[w][l*8+i];
    int pre=s;
    #pragma unroll
    for(int off=1;off<32;off<<=1){
      int o=__shfl_up_sync(0xFFFFFFFFu,pre,off);
      if(l>=off) pre+=o;
    }
    pre-=s; // exclusive prefix across lanes (bin-major order)
    int need=65-cbase;
    unsigned ball=__ballot_sync(0xFFFFFFFFu,(pre<need)&&(need<=pre+s));
    int ln=__ffs(ball)-1;
    int B=0,cb=0;
    if(l==ln){
      int run=pre,fb=-1;
      #pragma unroll
      for(int i=0;i<8;i++){
        int h=hist[w][l*8+i];
        if(fb<0){
          if(run+h>=need){ fb=l*8+i; cb=run; }
          else run+=h;
        }
      }
      B=fb;
    }
    B=__shfl_sync(0xFFFFFFFFu,B,ln);
    cb=__shfl_sync(0xFFFFFFFFu,cb,ln);
    cbase+=cb;             // FIX: accumulate global count strictly below new prefix
    pfx=(pfx<<8)|(unsigned)B;
  }

  // collect all keys with 24-bit prefix <= pfx  (>=65 of them, ~66 expected)
  if(l==0) cnt[w]=0;
  __syncwarp();
  for(int t0=0;t0<NP;t0+=2048){
    __syncthreads();
    for(int j=tid;j<2048;j+=256){
      int g=base+t0+j;
      tile[j]=make_float4(xyz[3*g],xyz[3*g+1],xyz[3*g+2],d_sq[g]);
    }
    __syncthreads();
    for(int j=l;j<2048;j+=32){
      float4 v=tile[j];
      float dot=fmaf(zi,v.z,fmaf(yi,v.y,__fmul_rn(xi,v.x)));
      float d=__fsub_rn(__fadd_rn(sqi,v.w),__fmul_rn(2.0f,dot));
      unsigned u=monof(d);
      if((u>>8)<=pfx){
        int s2=atomicAdd(&cnt[w],1);
        if(s2<128) buf[w][s2]=((ull)u<<32)|(unsigned)(t0+j);
      }
    }
  }
  __syncwarp();
  int c=cnt[w]; if(c>128)c=128;
  ull q0=(l<c)?buf[w][l]:~0ull;
  ull q1=(l+32<c)?buf[w][l+32]:~0ull;
  ull q2=(l+64<c)?buf[w][l+64]:~0ull;
  ull q3=(l+96<c)?buf[w][l+96]:~0ull;
  ull t;
  if(q0>q1){t=q0;q0=q1;q1=t;}
  if(q2>q3){t=q2;q2=q3;q3=t;}
  if(q0>q2){t=q0;q0=q2;q2=t;}
  if(q1>q3){t=q1;q1=q3;q3=t;}
  if(q1>q2){t=q1;q1=q2;q2=t;}
  int* o=d_cand+(long long)p*KC;
  for(int r=0;r<65;r++){
    ull bk=q0;
    #pragma unroll
    for(int off=16;off>0;off>>=1){
      ull ok=__shfl_xor_sync(0xFFFFFFFFu,bk,off);
      if(ok<bk) bk=ok;
    }
    if(r>0 && l==0) o[r-1]=(int)(bk&0xFFFFFFFFull);
    if(q0==bk){ q0=q1; q1=q2; q2=q3; q3=~0ull; }
  }
}

__device__ __forceinline__ float gelu_e(float x){
  return 0.5f*x*(1.0f+erff(x*0.70710678118654752440f));
}

// One block = 4 points. 4 warps x 2 groups x 8 candidates, f32x2 FMA.
__global__ __launch_bounds__(128) void k_mlp(
  const float* __restrict__ xyz,const float* __restrict__ feat,
  const float* __restrict__ b1,const float* __restrict__ w2,const float* __restrict__ b2)
{
  __shared__ float4 w1s[67*32];
  __shared__ float4 relq[4][136];
  __shared__ float w2s[128],b1s[128];
  __shared__ float sc[64];
  int tid=threadIdx.x,w=tid>>5,l=tid&31;
  for(int i=tid;i<67*32;i+=128) w1s[i]=d_w1q[i];
  if(tid<128){ w2s[tid]=w2[tid]; b1s[tid]=b1[tid]; }
  __syncthreads();
  float b2v=b2[0];
  int p0=blockIdx.x*4;
  int b=p0>>13,base=b*NP;

  for(int pi=0;pi<4;pi++){
    int p=p0+pi;
    float xi=xyz[3*p],yi=xyz[3*p+1],zi=xyz[3*p+2];
    float f0=feat[p*CF+l],f1=feat[p*CF+32+l];

    for(int g2=0;g2<2;g2++){
      int c0=w*16+g2*8;
      int gi[8];
      #pragma unroll
      for(int c=0;c<8;c++) gi[c]=base+d_cand[(long long)p*KC+c0+c];
      float fa[8],fb[8];
      #pragma unroll
      for(int c=0;c<8;c++){ fa[c]=feat[gi[c]*CF+l]; fb[c]=feat[gi[c]*CF+32+l]; }
      __syncwarp();
      #pragma unroll
      for(int c=0;c<8;c++){ fa[c]=__fsub_rn(fa[c],f0); fb[c]=__fsub_rn(fb[c],f1); }
      relq[w][(3+l)*2+0]=make_float4(fa[0],fa[1],fa[2],fa[3]);
      relq[w][(3+l)*2+1]=make_float4(fa[4],fa[5],fa[6],fa[7]);
      relq[w][(35+l)*2+0]=make_float4(fb[0],fb[1],fb[2],fb[3]);
      relq[w][(35+l)*2+1]=make_float4(fb[4],fb[5],fb[6],fb[7]);
      if(l<3){
        float self=(l==0)?xi:((l==1)?yi:zi);
        float rx[8];
        #pragma unroll
        for(int c=0;c<8;c++) rx[c]=__fsub_rn(xyz[3*gi[c]+l],self);
        relq[w][l*2+0]=make_float4(rx[0],rx[1],rx[2],rx[3]);
        relq[w][l*2+1]=make_float4(rx[4],rx[5],rx[6],rx[7]);
      }
      __syncwarp();

      ull acc[16];
      #pragma unroll
      for(int i=0;i<16;i++) acc[i]=0ull;
      #pragma unroll 4
      for(int k=0;k<67;k++){
        float4 wf=w1s[(k<<5)|l];
        float4 q0=relq[w][2*k],q1=relq[w][2*k+1];
        ull r01=pk2(q0.x,q0.y),r23=pk2(q0.z,q0.w);
        ull r45=pk2(q1.x,q1.y),r67=pk2(q1.z,q1.w);
        ull wx=dup2(wf.x),wy=dup2(wf.y),wz=dup2(wf.z),ww=dup2(wf.w);
        acc[0] =fma2(wx,r01,acc[0]);  acc[1] =fma2(wy,r01,acc[1]);
        acc[2] =fma2(wz,r01,acc[2]);  acc[3] =fma2(ww,r01,acc[3]);
        acc[4] =fma2(wx,r23,acc[4]);  acc[5] =fma2(wy,r23,acc[5]);
        acc[6] =fma2(wz,r23,acc[6]);  acc[7] =fma2(ww,r23,acc[7]);
        acc[8] =fma2(wx,r45,acc[8]);  acc[9] =fma2(wy,r45,acc[9]);
        acc[10]=fma2(wz,r45,acc[10]); acc[11]=fma2(ww,r45,acc[11]);
        acc[12]=fma2(wx,r67,acc[12]); acc[13]=fma2(wy,r67,acc[13]);
        acc[14]=fma2(wz,r67,acc[14]); acc[15]=fma2(ww,r67,acc[15]);
      }

      #pragma unroll
      for(int pr=0;pr<4;pr++){
        float v0l,v0h,v1l,v1h,v2l,v2h,v3l,v3h;
        unpk2(v0l,v0h,acc[pr*4+0]);
        unpk2(v1l,v1h,acc[pr*4+1]);
        unpk2(v2l,v2h,acc[pr*4+2]);
        unpk2(v3l,v3h,acc[pr*4+3]);
        #pragma unroll
        for(int half=0;half<2;half++){
          float a0=half?v0h:v0l,a1=half?v1h:v1l,a2=half?v2h:v2l,a3=half?v3h:v3l;
          float h0=gelu_e(a0+b1s[l]);
          float h1=gelu_e(a1+b1s[l+32]);
          float h2=gelu_e(a2+b1s[l+64]);
          float h3=gelu_e(a3+b1s[l+96]);
          float part=fmaf(h3,w2s[l+96],fmaf(h2,w2s[l+64],fmaf(h1,w2s[l+32],h0*w2s[l])));
          #pragma unroll
          for(int off=16;off>0;off>>=1) part+=__shfl_down_sync(0xFFFFFFFFu,part,off);
          if(l==0) sc[c0+2*pr+half]=part+b2v;
        }
      }
    }
    __syncthreads();
    if(tid==0){
      float bv[16]; int bi[16]; int cnt2=0;
      for(int c=0;c<KC;c++){
        float s=sc[c];
        if(cnt2<16){
          int pos=cnt2++;
          while(pos>0 && s>bv[pos-1]){ bv[pos]=bv[pos-1]; bi[pos]=bi[pos-1]; pos--; }
          bv[pos]=s; bi[pos]=c;
        } else if(s>bv[15]){
          int pos=15;
          while(pos>0 && s>bv[pos-1]){ bv[pos]=bv[pos-1]; bi[pos]=bi[pos-1]; pos--; }
          bv[pos]=s; bi[pos]=c;
        }
      }
      for(int r=0;r<KF;r++) d_fidx[(long long)p*KF+r]=d_cand[(long long)p*KC+bi[r]];
    }
    __syncthreads();
  }
}

__global__ __launch_bounds__(256) void k_curv(
  const float* __restrict__ xyz,const float* __restrict__ feat)
{
  int p=blockIdx.x*8+(threadIdx.x>>5);
  int l=threadIdx.x&31;
  int b=p>>13,base=b*NP;
  double c00=0,c01=0,c02=0,c11=0,c12=0,c22=0,fv=0;
  float cx=xyz[3*p],cy=xyz[3*p+1],cz=xyz[3*p+2];
  if(l<16){
    int g=base+d_fidx[(long long)p*KF+l];
    double dx=(double)__fsub_rn(xyz[3*g],cx);
    double dy=(double)__fsub_rn(xyz[3*g+1],cy);
    double dz=(double)__fsub_rn(xyz[3*g+2],cz);
    c00=dx*dx; c01=dx*dy; c02=dx*dz; c11=dy*dy; c12=dy*dz; c22=dz*dz;
    double s=0;
    for(int ch=0;ch<CF;ch++){
      float df=__fsub_rn(feat[g*CF+ch],feat[p*CF+ch]);
      s+=(double)df*(double)df;
    }
    fv=sqrt(s);
  }
  #pragma unroll
  for(int off=16;off>0;off>>=1){
    c00+=__shfl_down_sync(0xFFFFFFFFu,c00,off);
    c01+=__shfl_down_sync(0xFFFFFFFFu,c01,off);
    c02+=__shfl_down_sync(0xFFFFFFFFu,c02,off);
    c11+=__shfl_down_sync(0xFFFFFFFFu,c11,off);
    c12+=__shfl_down_sync(0xFFFFFFFFu,c12,off);
    c22+=__shfl_down_sync(0xFFFFFFFFu,c22,off);
    fv +=__shfl_down_sync(0xFFFFFFFFu,fv,off);
  }
  if(l==0){
    c00/=16.0;c01/=16.0;c02/=16.0;c11/=16.0;c12/=16.0;c22/=16.0;
    double q=(c00+c11+c22)/3.0;
    double p1=c01*c01+c02*c02+c12*c12;
    double p2=(c00-q)*(c00-q)+(c11-q)*(c11-q)+(c22-q)*(c22-q)+2.0*p1;
    double e0,e1,e2;
    if(p2<=0.0){ e0=e1=e2=q; }
    else{
      double pp=sqrt(p2/6.0),inv=1.0/pp;
      double b00=(c00-q)*inv,b11=(c11-q)*inv,b22=(c22-q)*inv;
      double b01=c01*inv,b02=c02*inv,b12=c12*inv;
      double detB=b00*(b11*b22-b12*b12)-b01*(b01*b22-b12*b02)+b02*(b01*b12-b11*b02);
      double r=detB*0.5; r=fmin(1.0,fmax(-1.0,r));
      double phi=acos(r)/3.0;
      e0=q+2.0*pp*cos(phi);
      e2=q+2.0*pp*cos(phi+2.0943951023931953);
      e1=3.0*q-e0-e2;
    }
    double s0=fabs(e0),s1=fabs(e1),s2=fabs(e2),t;
    if(s0<s1){t=s0;s0=s1;s1=t;}
    if(s1<s2){t=s1;s1=s2;s2=t;}
    if(s0<s1){t=s0;s0=s1;s1=t;}
    double l2=s0*s0,l1=s1*s1,l0=s2*s2;
    d_curv[p]=l0/(l0+l1+l2+1e-8);
    d_fv[p]=fv/16.0;
  }
}

__global__ __launch_bounds__(1024) void k_norm(){
  int b=blockIdx.x,tid=threadIdx.x;
  __shared__ double red[4][32];
  __shared__ double stats[4];
  double sc=0,sc2=0,sf=0,sf2=0;
  for(int u=0;u<8;u++){
    int i=b*NP+u*1024+tid;
    double c=d_curv[i],f=d_fv[i];
    sc+=c; sc2+=c*c; sf+=f; sf2+=f*f;
  }
  int w=tid>>5,l=tid&31;
  #pragma unroll
  for(int off=16;off>0;off>>=1){
    sc+=__shfl_down_sync(0xFFFFFFFFu,sc,off);
    sc2+=__shfl_down_sync(0xFFFFFFFFu,sc2,off);
    sf+=__shfl_down_sync(0xFFFFFFFFu,sf,off);
    sf2+=__shfl_down_sync(0xFFFFFFFFu,sf2,off);
  }
  if(l==0){ red[0][w]=sc; red[1][w]=sc2; red[2][w]=sf; red[3][w]=sf2; }
  __syncthreads();
  if(tid<32){
    double a=red[0][tid],bb=red[1][tid],c=red[2][tid],d=red[3][tid];
    #pragma unroll
    for(int off=16;off>0;off>>=1){
      a+=__shfl_down_sync(0xFFFFFFFFu,a,off);
      bb+=__shfl_down_sync(0xFFFFFFFFu,bb,off);
      c+=__shfl_down_sync(0xFFFFFFFFu,c,off);
      d+=__shfl_down_sync(0xFFFFFFFFu,d,off);
    }
    if(tid==0){
      double mc=a/NP,mf=c/NP;
      double vc=(bb-(double)NP*mc*mc)/(NP-1);
      double vf=(d-(double)NP*mf*mf)/(NP-1);
      stats[0]=mc; stats[1]=sqrt(fmax(vc,0.0));
      stats[2]=mf; stats[3]=sqrt(fmax(vf,0.0));
    }
  }
  __syncthreads();
  double mc=stats[0],sdc=stats[1],mf=stats[2],sdf=stats[3];
  for(int u=0;u<8;u++){
    int li=u*1024+tid,i=b*NP+li;
    double imp=(d_curv[i]-mc)/(sdc+1e-8)+0.5*((d_fv[i]-mf)/(sdf+1e-8));
    d_key[i]=monod(imp);
    d_kid[i]=li;
  }
}

__device__ __forceinline__ bool kgt(ull ka,int ia,ull kb,int ib){
  return ka>kb || (ka==kb && ia<ib);
}

__global__ __launch_bounds__(1024) void k_sortA(){
  __shared__ ull ks[2048];
  __shared__ int is[2048];
  int chunk=blockIdx.x;
  int b=chunk>>2,cb=(chunk&3)*2048,base=b*NP+cb;
  int tid=threadIdx.x;
  for(int i=tid;i<2048;i+=1024){ ks[i]=d_key[base+i]; is[i]=d_kid[base+i]; }
  for(int size=2;size<=2048;size<<=1){
    for(int st=size>>1;st>=1;st>>=1){
      __syncthreads();
      int i=((tid&~(st-1))<<1)|(tid&(st-1));
      int j=i+st;
      bool desc=(((cb+i)&size)==0);
      ull ka=ks[i],kb=ks[j]; int ia=is[i],ib=is[j];
      if(kgt(ka,ia,kb,ib)!=desc){ ks[i]=kb;is[i]=ib;ks[j]=ka;is[j]=ia; }
    }
  }
  __syncthreads();
  for(int i=tid;i<2048;i+=1024){ d_key[base+i]=ks[i]; d_kid[base+i]=is[i]; }
}

__global__ void k_gpass(int size,int stride){
  int t=blockIdx.x*blockDim.x+threadIdx.x;
  if(t>=NB*NP) return;
  int b=t>>13,i=t&(NP-1);
  int j=i^stride;
  if(j<=i) return;
  bool desc=((i&size)==0);
  int A=b*NP+i,Bx=b*NP+j;
  ull ka=d_key[A],kb=d_key[Bx];
  int ia=d_kid[A],ib=d_kid[Bx];
  if(kgt(ka,ia,kb,ib)!=desc){
    d_key[A]=kb; d_kid[A]=ib; d_key[Bx]=ka; d_kid[Bx]=ia;
  }
}

__global__ __launch_bounds__(1024) void k_spass(int size){
  __shared__ ull ks[2048];
  __shared__ int is[2048];
  int chunk=blockIdx.x;
  int b=chunk>>2,cb=(chunk&3)*2048,base=b*NP+cb;
  int tid=threadIdx.x;
  for(int i=tid;i<2048;i+=1024){ ks[i]=d_key[base+i]; is[i]=d_kid[base+i]; }
  int start=(size>>1)<1024?(size>>1):1024;
  for(int st=start;st>=1;st>>=1){
    __syncthreads();
    int i=((tid&~(st-1))<<1)|(tid&(st-1));
    int j=i+st;
    bool desc=(((cb+i)&size)==0);
    ull ka=ks[i],kb=ks[j]; int ia=is[i],ib=is[j];
    if(kgt(ka,ia,kb,ib)!=desc){ ks[i]=kb;is[i]=ib;ks[j]=ka;is[j]=ia; }
  }
  __syncthreads();
  for(int i=tid;i<2048;i+=1024){ d_key[base+i]=ks[i]; d_kid[base+i]=is[i]; }
}

__global__ void k_maskcopy(const float* __restrict__ xyz){
  int t=blockIdx.x*blockDim.x+threadIdx.x;
  if(t>=NB*NP) return;
  d_mask4[t]=make_float4(xyz[3*t],xyz[3*t+1],xyz[3*t+2],0.f);
}

__global__ void k_maskset(){
  int t=blockIdx.x*blockDim.x+threadIdx.x;
  if(t>=NB*1024) return;
  int b=t>>10,r=t&1023;
  int idx=d_kid[b*NP+r];
  d_cidx[t]=idx;
  float far=unmonof(d_maxb)+1.0f;
  d_mask4[b*NP+idx]=make_float4(far,far,far,0.f);
}

__global__ __launch_bounds__(512) void k_fps(){
  int b=blockIdx.x,tid=threadIdx.x,base=b*NP;
  __shared__ ull red[2][16];
  int w=tid>>5,l=tid&31;
  float px[16],py[16],pz[16],md[16];
  unsigned nidx[16];
  #pragma unroll
  for(int u=0;u<16;u++){
    float4 v=d_mask4[base+u*512+tid];
    px[u]=v.x; py[u]=v.y; pz[u]=v.z;
    md[u]=1e10f;
    nidx[u]=~(unsigned)(u*512+tid);
  }
  if(tid==0) d_fpsi[b*1024]=0;
  float4 pv=d_mask4[base];
  float lx=pv.x,ly=pv.y,lz=pv.z;
  for(int s=1;s<1024;s++){
    ull ku[16];
    #pragma unroll
    for(int u=0;u<16;u++){
      float dx=__fsub_rn(px[u],lx),dy=__fsub_rn(py[u],ly),dz=__fsub_rn(pz[u],lz);
      float d=__fadd_rn(__fadd_rn(__fmul_rn(dx,dx),__fmul_rn(dy,dy)),__fmul_rn(dz,dz));
      md[u]=fminf(md[u],d);
      ku[u]=((ull)__float_as_uint(md[u])<<32)|nidx[u];
    }
    #pragma unroll
    for(int st=8;st>0;st>>=1)
      #pragma unroll
      for(int u=0;u<16;u++) if(u<st && ku[u+st]>ku[u]) ku[u]=ku[u+st];
    ull best=ku[0];
    #pragma unroll
    for(int off=16;off>0;off>>=1){
      ull o=__shfl_down_sync(0xFFFFFFFFu,best,off);
      if(o>best) best=o;
    }
    if(l==0) red[s&1][w]=best;
    __syncthreads();
    ull v=red[s&1][l&15];
    #pragma unroll
    for(int off=8;off>0;off>>=1){
      ull o=__shfl_xor_sync(0xFFFFFFFFu,v,off);
      if(o>v) v=o;
    }
    unsigned wi=~(unsigned)(v&0xFFFFFFFFull);
    if(tid==0) d_fpsi[b*1024+s]=(int)wi;
    float4 nv=d_mask4[base+wi];
    lx=nv.x; ly=nv.y; lz=nv.z;
  }
}

__global__ void k_out(const float* __restrict__ xyz,float* __restrict__ out,int out_size){
  int t=blockIdx.x*blockDim.x+threadIdx.x;
  if(t>=NB*2048) return;
  int b=t>>11,r=t&2047;
  int idx=(r<1024)?d_cidx[b*1024+r]:d_fpsi[b*1024+(r-1024)];
  int g=b*NP+idx;
  if(out_size>=NB*2048*3){
    out[3*t]=xyz[3*g]; out[3*t+1]=xyz[3*g+1]; out[3*t+2]=xyz[3*g+2];
  }
  if(out_size>=NB*2048*4){
    out[NB*2048*3+t]=(float)idx;
  }
}

extern "C" void kernel_launch(void* const* d_in, const int* in_sizes, int n_in,
                              void* d_out, int out_size) {
  const float* xyz =(const float*)d_in[0];
  const float* feat=(const float*)d_in[1];
  const float* w1  =(const float*)d_in[2];
  const float* b1  =(const float*)d_in[3];
  const float* w2  =(const float*)d_in[4];
  const float* b2  =(const float*)d_in[5];
  float* out=(float*)d_out;

  k_initw<<<(67*32+255)/256,256>>>(w1);
  k_prep<<<(NB*NP+255)/256,256>>>(xyz);
  k_knn<<<NB*NP/8,256>>>(xyz);
  k_mlp<<<NB*NP/4,128>>>(xyz,feat,b1,w2,b2);
  k_curv<<<NB*NP/8,256>>>(xyz,feat);
  k_norm<<<NB,1024>>>();
  k_sortA<<<NB*4,1024>>>();
  k_gpass<<<(NB*NP+255)/256,256>>>(4096,2048);
  k_spass<<<NB*4,1024>>>(4096);
  k_gpass<<<(NB*NP+255)/256,256>>>(8192,4096);
  k_gpass<<<(NB*NP+255)/256,256>>>(8192,2048);
  k_spass<<<NB*4,1024>>>(8192);
  k_maskcopy<<<(NB*NP+255)/256,256>>>(xyz);
  k_maskset<<<(NB*1024+255)/256,256>>>();
  k_fps<<<NB,512>>>();
  k_out<<<(NB*2048+255)/256,256>>>(xyz,out,out_size);
}